// round 15
// baseline (speedup 1.0000x reference)
#include <cuda_runtime.h>

// out[(b*8+h)*Np1^2 + r*Np1 + c] =
//   token[h]                                   if r==0 || c==0
//   emb[ st[(b*N + (r-1))*N + (c-1)] ][h]      otherwise
//
// Block = 512 threads, processes ROWS_PER_BLOCK=8 consecutive output rows
// (b,r). emb staged ONCE per block (pitch 9*float4 -> uniform quad-bank
// groups for random stv). Thread tid owns column c = tid+1 of each row and
// writes all 8 h-planes. Next row's st LDG is prefetched before the current
// row's gather+stores (MLP=2 on the critical chain). Zero 64-bit math.

#define ROWS_PER_BLOCK 8

__global__ void __launch_bounds__(512)
wbe_rows8(const int* __restrict__ st,
          const float* __restrict__ emb,
          const float* __restrict__ token,
          float* __restrict__ out,
          int B, int N, int embRows, int totalRows)
{
    extern __shared__ float sh[];            // embRows*36 floats, then 8 token floats
    float* s_tok = sh + embRows * 36;

    const int tid = threadIdx.x;
    const int nsh = embRows * 8;
    for (int i = tid; i < nsh; i += blockDim.x) {
        int s = i >> 3, h = i & 7;
        sh[s * 36 + h] = emb[i];             // emb row s at float4 slot s*9
    }
    if (tid < 8) s_tok[tid] = token[tid];
    __syncthreads();

    const int Np1   = N + 1;
    const int plane = Np1 * Np1;

    int rid    = blockIdx.x * ROWS_PER_BLOCK;
    int ridEnd = rid + ROWS_PER_BLOCK;
    if (ridEnd > totalRows) ridEnd = totalRows;
    if (rid >= ridEnd) return;

    // prefetch first row
    int b = rid / Np1;
    int r = rid - b * Np1;
    int stv = 0;
    if (r > 0) stv = __ldg(&st[(b * N + (r - 1)) * N + tid]);

    while (rid < ridEnd) {
        const int b_cur = b, r_cur = r, stv_cur = stv;

        // prefetch next row's st value (overlaps this row's gather+stores)
        const int ridn = rid + 1;
        if (ridn < ridEnd) {
            b = ridn / Np1;
            r = ridn - b * Np1;
            if (r > 0) stv = __ldg(&st[(b * N + (r - 1)) * N + tid]);
        }

        const int obase = (b_cur * 8) * plane + r_cur * Np1;
        float vals[8];
        if (r_cur == 0) {
            #pragma unroll
            for (int h = 0; h < 8; ++h) vals[h] = s_tok[h];
        } else {
            const float4* e4 = reinterpret_cast<const float4*>(sh) + stv_cur * 9;
            float4 v0 = e4[0];
            float4 v1 = e4[1];
            vals[0] = v0.x; vals[1] = v0.y; vals[2] = v0.z; vals[3] = v0.w;
            vals[4] = v1.x; vals[5] = v1.y; vals[6] = v1.z; vals[7] = v1.w;
        }

        float* p = out + obase + tid + 1;    // c = tid+1
        #pragma unroll
        for (int h = 0; h < 8; ++h) {
            *p = vals[h];
            p += plane;
        }
        if (tid == 0) {                      // c == 0 token column
            float* q = out + obase;
            #pragma unroll
            for (int h = 0; h < 8; ++h) {
                *q = s_tok[h];
                q += plane;
            }
        }
        rid = ridn;
    }
}

// Generic fallback (safety net for unexpected shapes)
__global__ void wbe_kernel_generic(const int* __restrict__ st,
                                   const float* __restrict__ emb,
                                   const float* __restrict__ token,
                                   float* __restrict__ out,
                                   int B, int N, int H, int embRows,
                                   long long total)
{
    extern __shared__ float sh[];
    float* s_emb = sh;
    float* s_tok = sh + (size_t)embRows * H;
    const int nsh = embRows * H;
    for (int i = threadIdx.x; i < nsh; i += blockDim.x) s_emb[i] = emb[i];
    for (int i = threadIdx.x; i < H; i += blockDim.x) s_tok[i] = token[i];
    __syncthreads();

    long long idx = (long long)blockIdx.x * blockDim.x + threadIdx.x;
    if (idx >= total) return;

    const int Np1 = N + 1;
    int c = (int)(idx % Np1);
    long long t = idx / Np1;
    int r = (int)(t % Np1);
    int bb = (int)(t / Np1);

    const float* src;
    if (r == 0 || c == 0) {
        src = s_tok;
    } else {
        int stv = st[((long long)bb * N + (r - 1)) * N + (c - 1)];
        src = s_emb + (size_t)stv * H;
    }
    const long long plane = (long long)Np1 * Np1;
    long long o = ((long long)bb * H) * plane + (long long)r * Np1 + c;
    for (int hh = 0; hh < H; ++hh)
        out[o + (long long)hh * plane] = src[hh];
}

extern "C" void kernel_launch(void* const* d_in, const int* in_sizes, int n_in,
                              void* d_out, int out_size)
{
    // inputs (metadata order):
    // 0: spatial_types [E] int32, 1: graph_index [2,E] int32, 2: batch [B*N] int32,
    // 3: num_graphs, 4: max_nodes, 5: emb_weight [(S+1),H] f32, 6: graph_token [1,H,1] f32
    const int*   st    = (const int*)  d_in[0];
    const float* emb   = (const float*)d_in[5];
    const float* token = (const float*)d_in[6];
    float* out = (float*)d_out;

    const long long E = in_sizes[0];
    const int num_nodes = in_sizes[2];
    const int H = in_sizes[6];
    const int embRows = in_sizes[5] / H;
    const int N = (int)(E / num_nodes);   // E = B*N*N, num_nodes = B*N
    const int B = num_nodes / N;
    const int Np1 = N + 1;
    const int totalRows = B * Np1;

    if (H == 8 && N == 512 && embRows <= 1024 &&
        (long long)B * H * Np1 * Np1 < (1LL << 31)) {
        const int blocks = (totalRows + ROWS_PER_BLOCK - 1) / ROWS_PER_BLOCK;
        const size_t smem = (size_t)(embRows * 36 + 8) * sizeof(float);
        wbe_rows8<<<blocks, 512, smem>>>(st, emb, token, out, B, N, embRows, totalRows);
    } else {
        const long long total = (long long)B * Np1 * Np1;
        const int threads = 256;
        const long long blocks = (total + threads - 1) / threads;
        const size_t smem = ((size_t)embRows * H + H) * sizeof(float);
        wbe_kernel_generic<<<(unsigned)blocks, threads, smem>>>(
            st, emb, token, out, B, N, H, embRows, total);
    }
}